// round 1
// baseline (speedup 1.0000x reference)
#include <cuda_runtime.h>
#include <math.h>

#define THREADS 256
#define ROWS    64      // batch rows per CTA
#define HDIM    64
#define HS      64      // row stride for all shared 2D buffers (floats)
#define DDIM    784
#define KC      56      // k-chunk for input GEMM (784 = 14*56)
#define KOUT    10
#define EPSGN   1e-5f

// 4x4 register-tile GEMM over shared operands.
// A: [rows][HS] linear. Bt: [col][HS] either linear or float4-slot swizzled.
// Swizzle: element (row,k) lives at row*64 + (((k>>2) ^ (row>>2)) & 15)*4 + (k&3).
template<int KCNT, bool SWZ>
__device__ __forceinline__ void gemm4x4(const float* __restrict__ A,
                                        const float* __restrict__ Bt,
                                        int r0, int c0, float acc[4][4]) {
#pragma unroll 4
    for (int k = 0; k < KCNT; k += 4) {
        float4 a[4], w[4];
#pragma unroll
        for (int i = 0; i < 4; ++i)
            a[i] = *reinterpret_cast<const float4*>(A + (r0 + i) * HS + k);
#pragma unroll
        for (int j = 0; j < 4; ++j) {
            int row = c0 + j;
            int off;
            if (SWZ) {
                int slot = ((k >> 2) ^ (row >> 2)) & 15;
                off = row * HS + (slot << 2);
            } else {
                off = row * HS + k;
            }
            w[j] = *reinterpret_cast<const float4*>(Bt + off);
        }
#pragma unroll
        for (int i = 0; i < 4; ++i)
#pragma unroll
            for (int j = 0; j < 4; ++j) {
                acc[i][j] += a[i].x * w[j].x;
                acc[i][j] += a[i].y * w[j].y;
                acc[i][j] += a[i].z * w[j].z;
                acc[i][j] += a[i].w * w[j].w;
            }
    }
}

__device__ __forceinline__ int swz_off(int row, int k) {
    int slot = ((k >> 2) ^ (row >> 2)) & 15;
    return row * HS + (slot << 2) + (k & 3);
}

__global__ __launch_bounds__(THREADS, 2)
void node_fused_kernel(const float* __restrict__ x,
                       const float* __restrict__ W_in,
                       const float* __restrict__ b_in,
                       const float* __restrict__ g1,
                       const float* __restrict__ be1,
                       const float* __restrict__ W1,
                       const float* __restrict__ b1,
                       const float* __restrict__ W2,
                       const float* __restrict__ b2,
                       const float* __restrict__ g2,
                       const float* __restrict__ be2,
                       const float* __restrict__ W_out,
                       const float* __restrict__ b_out,
                       const int* __restrict__ nsp,
                       float* __restrict__ out)
{
    extern __shared__ float sm[];
    float* sH   = sm;                     // [64][64] current h
    float* sAcc = sH   + ROWS * HS;       // [64][64] RK4 accumulator
    float* sTmp = sAcc + ROWS * HS;       // [64][64] htmp / x-chunk / logits
    float* sU   = sTmp + ROWS * HS;       // [64][64] tanh intermediate / Wt-chunk / gn2
    float* sW1  = sU   + ROWS * HS;       // [64][64] W1^T swizzled
    float* sW2  = sW1  + HDIM * HS;       // [64][64] W2^T swizzled
    float* sWo  = sW2  + HDIM * HS;       // [10][64] W_out^T
    float* sB1  = sWo  + KOUT * HDIM;     // [64]
    float* sB2  = sB1  + HDIM;            // [64]

    const int tid  = threadIdx.x;
    const int rowg = tid >> 4;
    const int colg = tid & 15;
    const int r0   = rowg * 4;
    const int c0   = colg * 4;
    const long long row0 = (long long)blockIdx.x * ROWS;

    // ------------- stage ODE + output weights (regions unused by GEMM1) ------
    for (int idx = tid; idx < HDIM * HDIM; idx += THREADS) {
        int k = idx >> 6, j = idx & 63;
        sW1[swz_off(j, k)] = W1[k * HDIM + j];
        sW2[swz_off(j, k)] = W2[k * HDIM + j];
    }
    for (int idx = tid; idx < KOUT * HDIM; idx += THREADS) {
        int k = idx / KOUT, c = idx % KOUT;
        sWo[c * HDIM + k] = W_out[k * KOUT + c];
    }
    if (tid < HDIM) { sB1[tid] = b1[tid]; sB2[tid] = b2[tid]; }

    // ------------- GEMM1: h_pre = x @ W_in  (k-chunked through smem) ---------
    float acc[4][4] = {};
    for (int ch = 0; ch < DDIM / KC; ++ch) {
        // stage x chunk -> sTmp (linear, rows of KC floats at stride HS)
        for (int idx = tid; idx < ROWS * (KC / 4); idx += THREADS) {
            int r = idx / (KC / 4), kv = idx % (KC / 4);
            *reinterpret_cast<float4*>(sTmp + r * HS + kv * 4) =
                *reinterpret_cast<const float4*>(
                    x + (row0 + r) * DDIM + ch * KC + kv * 4);
        }
        // stage W_in chunk transposed+swizzled -> sU
        for (int idx = tid; idx < KC * HDIM; idx += THREADS) {
            int k = idx >> 6, j = idx & 63;
            sU[swz_off(j, k)] = W_in[(ch * KC + k) * HDIM + j];
        }
        __syncthreads();
        gemm4x4<KC, true>(sTmp, sU, r0, c0, acc);
        __syncthreads();
    }
#pragma unroll
    for (int i = 0; i < 4; ++i)
#pragma unroll
        for (int j = 0; j < 4; ++j)
            sH[(r0 + i) * HS + c0 + j] = acc[i][j] + b_in[c0 + j];
    __syncthreads();

    // ------------- GroupNorm1 + tanh -----------------------------------------
    for (int t = tid; t < ROWS * 8; t += THREADS) {
        int r = t >> 3, g = t & 7;
        float* p = sH + r * HS + g * 8;
        float mu = 0.f;
#pragma unroll
        for (int i = 0; i < 8; ++i) mu += p[i];
        mu *= 0.125f;
        float var = 0.f;
#pragma unroll
        for (int i = 0; i < 8; ++i) { float d = p[i] - mu; var += d * d; }
        var *= 0.125f;
        float rs = rsqrtf(var + EPSGN);
#pragma unroll
        for (int i = 0; i < 8; ++i) {
            int c = g * 8 + i;
            p[i] = tanhf((p[i] - mu) * rs * g1[c] + be1[c]);
        }
    }
    __syncthreads();

    // ------------- RK4 integration -------------------------------------------
    const int   nsteps = *nsp;
    const float dt = 1.0f / (float)nsteps;

    float kr[4][4];
    auto feval = [&](const float* src) {
        float a2[4][4] = {};
        gemm4x4<HDIM, true>(src, sW1, r0, c0, a2);
#pragma unroll
        for (int i = 0; i < 4; ++i)
#pragma unroll
            for (int j = 0; j < 4; ++j)
                sU[(r0 + i) * HS + c0 + j] = tanhf(a2[i][j] + sB1[c0 + j]);
        __syncthreads();
        float b2r[4][4] = {};
        gemm4x4<HDIM, true>(sU, sW2, r0, c0, b2r);
#pragma unroll
        for (int i = 0; i < 4; ++i)
#pragma unroll
            for (int j = 0; j < 4; ++j)
                kr[i][j] = b2r[i][j] + sB2[c0 + j];
    };

    for (int s = 0; s < nsteps; ++s) {
        // k1
        feval(sH);
#pragma unroll
        for (int i = 0; i < 4; ++i)
#pragma unroll
            for (int j = 0; j < 4; ++j) {
                int o = (r0 + i) * HS + c0 + j;
                float h = sH[o], k = kr[i][j];
                sAcc[o] = h + (dt / 6.f) * k;
                sTmp[o] = h + (0.5f * dt) * k;
            }
        __syncthreads();
        // k2
        feval(sTmp);
#pragma unroll
        for (int i = 0; i < 4; ++i)
#pragma unroll
            for (int j = 0; j < 4; ++j) {
                int o = (r0 + i) * HS + c0 + j;
                float k = kr[i][j];
                sAcc[o] += (dt / 3.f) * k;
                sTmp[o] = sH[o] + (0.5f * dt) * k;
            }
        __syncthreads();
        // k3
        feval(sTmp);
#pragma unroll
        for (int i = 0; i < 4; ++i)
#pragma unroll
            for (int j = 0; j < 4; ++j) {
                int o = (r0 + i) * HS + c0 + j;
                float k = kr[i][j];
                sAcc[o] += (dt / 3.f) * k;
                sTmp[o] = sH[o] + dt * k;
            }
        __syncthreads();
        // k4
        feval(sTmp);
#pragma unroll
        for (int i = 0; i < 4; ++i)
#pragma unroll
            for (int j = 0; j < 4; ++j) {
                int o = (r0 + i) * HS + c0 + j;
                sH[o] = sAcc[o] + (dt / 6.f) * kr[i][j];
            }
        __syncthreads();
    }

    // ------------- GroupNorm2 -> sU -------------------------------------------
    for (int t = tid; t < ROWS * 8; t += THREADS) {
        int r = t >> 3, g = t & 7;
        const float* p = sH + r * HS + g * 8;
        float* q = sU + r * HS + g * 8;
        float mu = 0.f;
#pragma unroll
        for (int i = 0; i < 8; ++i) mu += p[i];
        mu *= 0.125f;
        float var = 0.f;
#pragma unroll
        for (int i = 0; i < 8; ++i) { float d = p[i] - mu; var += d * d; }
        var *= 0.125f;
        float rs = rsqrtf(var + EPSGN);
#pragma unroll
        for (int i = 0; i < 8; ++i) {
            int c = g * 8 + i;
            q[i] = (p[i] - mu) * rs * g2[c] + be2[c];
        }
    }
    __syncthreads();

    // ------------- output projection: logits -> sTmp --------------------------
    for (int t = tid; t < ROWS * KOUT; t += THREADS) {
        int r = t / KOUT, c = t % KOUT;
        const float* hr = sU + r * HS;
        const float* wc = sWo + c * HDIM;
        float s = 0.f;
#pragma unroll 8
        for (int k = 0; k < HDIM; ++k) s += hr[k] * wc[k];
        sTmp[r * HS + c] = s + b_out[c];
    }
    __syncthreads();

    // ------------- log_softmax + write ----------------------------------------
    for (int r = tid; r < ROWS; r += THREADS) {
        const float* lg = sTmp + r * HS;
        float mx = lg[0];
#pragma unroll
        for (int c = 1; c < KOUT; ++c) mx = fmaxf(mx, lg[c]);
        float se = 0.f;
#pragma unroll
        for (int c = 0; c < KOUT; ++c) se += expf(lg[c] - mx);
        float lse = mx + logf(se);
        float* o = out + (row0 + r) * KOUT;
#pragma unroll
        for (int c = 0; c < KOUT; ++c) o[c] = lg[c] - lse;
    }
}

extern "C" void kernel_launch(void* const* d_in, const int* in_sizes, int n_in,
                              void* d_out, int out_size) {
    const float* x     = (const float*)d_in[0];
    const float* W_in  = (const float*)d_in[1];
    const float* b_in  = (const float*)d_in[2];
    const float* g1    = (const float*)d_in[3];
    const float* be1   = (const float*)d_in[4];
    const float* W1    = (const float*)d_in[5];
    const float* b1    = (const float*)d_in[6];
    const float* W2    = (const float*)d_in[7];
    const float* b2    = (const float*)d_in[8];
    const float* g2    = (const float*)d_in[9];
    const float* be2   = (const float*)d_in[10];
    const float* W_out = (const float*)d_in[11];
    const float* b_out = (const float*)d_in[12];
    const int*   nsp   = (const int*)d_in[13];
    float* out = (float*)d_out;

    const int B = in_sizes[0] / DDIM;
    const int nblk = B / ROWS;

    const size_t smem = (size_t)(6 * ROWS * HS + KOUT * HDIM + 2 * HDIM) * sizeof(float);
    cudaFuncSetAttribute(node_fused_kernel,
                         cudaFuncAttributeMaxDynamicSharedMemorySize, (int)smem);

    node_fused_kernel<<<nblk, THREADS, smem>>>(
        x, W_in, b_in, g1, be1, W1, b1, W2, b2, g2, be2, W_out, b_out, nsp, out);
}

// round 3
// speedup vs baseline: 2.4508x; 2.4508x over previous
#include <cuda_runtime.h>
#include <cuda_bf16.h>
#include <stdint.h>

#define THREADS 256
#define ROWSB   128

// ---- shared memory float offsets ----
#define PAR_BIN  0
#define PAR_G1   64
#define PAR_BE1  128
#define PAR_B1   192
#define PAR_B2   256
#define PAR_G2   320
#define PAR_BE2  384
#define PAR_BOUT 448
#define PAR_WOUT 464                     // 640 floats -> ends 1104
#define OFF_XS   1120                    // x stage: 128 rows * 72 floats
#define OFF_WA   (OFF_XS + 128*72)       // W_in-chunk / W1 frags: hi 2048 + lo 2048 words
#define OFF_WB   (OFF_WA + 4096)         // W2 frags: hi 2048 + lo 2048 words
#define SMEM_FLOATS (OFF_WB + 4096)      // 18528 floats = 74112 B

__device__ __forceinline__ uint32_t packbf(float lo, float hi) {
    __nv_bfloat162 t = __floats2bfloat162_rn(lo, hi);
    return *reinterpret_cast<uint32_t*>(&t);
}
// split (v0,v1) into bf16 hi pack + bf16 residual-lo pack (lo halves = v0)
__device__ __forceinline__ void split2(float v0, float v1, uint32_t& hi, uint32_t& lo) {
    float h0 = __bfloat162float(__float2bfloat16_rn(v0));
    float h1 = __bfloat162float(__float2bfloat16_rn(v1));
    hi = packbf(h0, h1);
    lo = packbf(v0 - h0, v1 - h1);
}
__device__ __forceinline__ void mma16816(float* c, const uint32_t* a, uint32_t b0, uint32_t b1) {
    asm volatile(
        "mma.sync.aligned.m16n8k16.row.col.f32.bf16.bf16.f32 "
        "{%0,%1,%2,%3}, {%4,%5,%6,%7}, {%8,%9}, {%0,%1,%2,%3};\n"
        : "+f"(c[0]), "+f"(c[1]), "+f"(c[2]), "+f"(c[3])
        : "r"(a[0]), "r"(a[1]), "r"(a[2]), "r"(a[3]), "r"(b0), "r"(b1));
}
// accurate-enough tanh: 1 - 2/(exp2(2x*log2e)+1); graceful at +-inf
__device__ __forceinline__ float tanhfast(float x) {
    float e;
    asm("ex2.approx.f32 %0, %1;" : "=f"(e) : "f"(x * 2.8853900817779268f));
    float d = e + 1.0f, i;
    asm("rcp.approx.f32 %0, %1;" : "=f"(i) : "f"(d));
    return fmaf(-2.0f, i, 1.0f);
}

// one 64-feature GEMM: C[16x64 per warp] = v @ W, 3-term bf16 split, W frags in smem
__device__ __forceinline__ void gemm64(const float v[8][4],
                                       const uint32_t* __restrict__ wHi,
                                       const uint32_t* __restrict__ wLo,
                                       float c[8][4], int q, int r) {
#pragma unroll
    for (int j = 0; j < 8; ++j) { c[j][0]=0.f; c[j][1]=0.f; c[j][2]=0.f; c[j][3]=0.f; }
#pragma unroll
    for (int t = 0; t < 4; ++t) {
        uint32_t aHi[4], aLo[4];
        split2(v[2*t][0],   v[2*t][1],   aHi[0], aLo[0]);   // row r,   k 2q..2q+1
        split2(v[2*t][2],   v[2*t][3],   aHi[1], aLo[1]);   // row r+8
        split2(v[2*t+1][0], v[2*t+1][1], aHi[2], aLo[2]);   // row r,   k +8
        split2(v[2*t+1][2], v[2*t+1][3], aHi[3], aLo[3]);   // row r+8, k +8
        int base = (t*32 + q)*16 + r*2;
#pragma unroll
        for (int j = 0; j < 8; ++j) {
            int idx = base + j*64;
            uint2 bh = *reinterpret_cast<const uint2*>(wHi + idx);
            uint2 bl = *reinterpret_cast<const uint2*>(wLo + idx);
            mma16816(c[j], aHi, bh.x, bh.y);
            mma16816(c[j], aHi, bl.x, bl.y);
            mma16816(c[j], aLo, bh.x, bh.y);
        }
    }
}

__global__ __launch_bounds__(THREADS)
void node_mma_kernel(const float* __restrict__ x,
                     const float* __restrict__ W_in,
                     const float* __restrict__ b_in,
                     const float* __restrict__ g1,
                     const float* __restrict__ be1,
                     const float* __restrict__ W1,
                     const float* __restrict__ b1,
                     const float* __restrict__ W2,
                     const float* __restrict__ b2,
                     const float* __restrict__ g2,
                     const float* __restrict__ be2,
                     const float* __restrict__ W_out,
                     const float* __restrict__ b_out,
                     const int* __restrict__ nsp,
                     float* __restrict__ out)
{
    extern __shared__ float sm[];
    uint32_t* waHi = reinterpret_cast<uint32_t*>(sm + OFF_WA);
    uint32_t* waLo = waHi + 2048;
    uint32_t* wbHi = reinterpret_cast<uint32_t*>(sm + OFF_WB);
    uint32_t* wbLo = wbHi + 2048;
    float* xs = sm + OFF_XS;

    const int tid  = threadIdx.x;
    const int lane = tid & 31;
    const int wid  = tid >> 5;
    const int q    = lane & 3;      // col-pair within n-tile / k-pair selector
    const int r    = lane >> 2;     // row within m-half
    const int R0   = wid * 16;      // warp's row base in CTA tile
    const long long row0 = (long long)blockIdx.x * ROWSB;

    // ---- stage params ----
    for (int i = tid; i < 64; i += THREADS) {
        sm[PAR_BIN+i]=b_in[i]; sm[PAR_G1+i]=g1[i]; sm[PAR_BE1+i]=be1[i];
        sm[PAR_B1+i]=b1[i];    sm[PAR_B2+i]=b2[i];
        sm[PAR_G2+i]=g2[i];    sm[PAR_BE2+i]=be2[i];
    }
    if (tid < 10) sm[PAR_BOUT+tid] = b_out[tid];
    for (int i = tid; i < 640; i += THREADS) sm[PAR_WOUT+i] = W_out[i];

    // ---- GEMM1: h_pre = x @ W_in, k chunked (12x64 + 1x16) ----
    float c[8][4];
#pragma unroll
    for (int j = 0; j < 8; ++j) { c[j][0]=0.f; c[j][1]=0.f; c[j][2]=0.f; c[j][3]=0.f; }

    for (int ck = 0; ck < 13; ++ck) {
        const int kbase = ck * 64;
        const int kcur  = (ck < 12) ? 64 : 16;
        const int kt    = kcur >> 4;
        __syncthreads();
        // stage x chunk (fp32, row stride 72 for conflict-free frag reads)
        const int nf4 = ROWSB * (kcur >> 2);
        for (int f = tid; f < nf4; f += THREADS) {
            int row = f / (kcur >> 2);
            int c4  = f % (kcur >> 2);
            float4 v = *reinterpret_cast<const float4*>(x + (row0+row)*784 + kbase + c4*4);
            float* d = xs + row*72 + c4*4;
            d[0]=v.x; d[1]=v.y; d[2]=v.z; d[3]=v.w;
        }
        // build W_in chunk B-fragments (hi/lo packed words)
        const int np = kt * 512;
        for (int p = tid; p < np; p += THREADS) {
            int half=p&1, rr=(p>>1)&7, qq=(p>>4)&3, jj=(p>>6)&7, tt=(p>>9)&3;
            int k0 = kbase + 16*tt + 8*half + 2*qq;
            int n  = 8*jj + rr;
            split2(W_in[k0*64+n], W_in[(k0+1)*64+n], waHi[p], waLo[p]);
        }
        __syncthreads();
        for (int t = 0; t < kt; ++t) {
            uint32_t aHi[4], aLo[4];
            const float* ra = xs + (R0 + r)*72 + 16*t + 2*q;
            const float* rb = ra + 8*72;
            float2 v00 = *reinterpret_cast<const float2*>(ra);
            float2 v01 = *reinterpret_cast<const float2*>(ra + 8);
            float2 v10 = *reinterpret_cast<const float2*>(rb);
            float2 v11 = *reinterpret_cast<const float2*>(rb + 8);
            split2(v00.x, v00.y, aHi[0], aLo[0]);
            split2(v10.x, v10.y, aHi[1], aLo[1]);
            split2(v01.x, v01.y, aHi[2], aLo[2]);
            split2(v11.x, v11.y, aHi[3], aLo[3]);
            int base = (t*32 + q)*16 + r*2;
#pragma unroll
            for (int j = 0; j < 8; ++j) {
                int idx = base + j*64;
                uint2 bh = *reinterpret_cast<const uint2*>(waHi + idx);
                uint2 bl = *reinterpret_cast<const uint2*>(waLo + idx);
                mma16816(c[j], aHi, bh.x, bh.y);
                mma16816(c[j], aHi, bl.x, bl.y);
                mma16816(c[j], aLo, bh.x, bh.y);
            }
        }
    }

    // ---- bias + GroupNorm1 + tanh (registers + quad shuffles) ----
    float h[8][4];
#pragma unroll
    for (int j = 0; j < 8; ++j) {
        float2 bb = *reinterpret_cast<const float2*>(sm + PAR_BIN + 8*j + 2*q);
        h[j][0] = c[j][0] + bb.x; h[j][1] = c[j][1] + bb.y;
        h[j][2] = c[j][2] + bb.x; h[j][3] = c[j][3] + bb.y;
    }
#pragma unroll
    for (int j = 0; j < 8; ++j) {
        float s1 = h[j][0] + h[j][1], s2 = h[j][0]*h[j][0] + h[j][1]*h[j][1];
        float t1 = h[j][2] + h[j][3], t2 = h[j][2]*h[j][2] + h[j][3]*h[j][3];
        s1 += __shfl_xor_sync(~0u, s1, 1); s1 += __shfl_xor_sync(~0u, s1, 2);
        s2 += __shfl_xor_sync(~0u, s2, 1); s2 += __shfl_xor_sync(~0u, s2, 2);
        t1 += __shfl_xor_sync(~0u, t1, 1); t1 += __shfl_xor_sync(~0u, t1, 2);
        t2 += __shfl_xor_sync(~0u, t2, 1); t2 += __shfl_xor_sync(~0u, t2, 2);
        float muA = s1*0.125f, vA = fmaxf(s2*0.125f - muA*muA, 0.f);
        float muB = t1*0.125f, vB = fmaxf(t2*0.125f - muB*muB, 0.f);
        float rsA = rsqrtf(vA + 1e-5f), rsB = rsqrtf(vB + 1e-5f);
        float2 gg = *reinterpret_cast<const float2*>(sm + PAR_G1  + 8*j + 2*q);
        float2 be = *reinterpret_cast<const float2*>(sm + PAR_BE1 + 8*j + 2*q);
        h[j][0] = tanhfast((h[j][0]-muA)*rsA*gg.x + be.x);
        h[j][1] = tanhfast((h[j][1]-muA)*rsA*gg.y + be.y);
        h[j][2] = tanhfast((h[j][2]-muB)*rsB*gg.x + be.x);
        h[j][3] = tanhfast((h[j][3]-muB)*rsB*gg.y + be.y);
    }

    // ---- stage W1/W2 B-fragments (reuse/overwrite W_in region) ----
    __syncthreads();
    for (int p = tid; p < 2048; p += THREADS) {
        int half=p&1, rr=(p>>1)&7, qq=(p>>4)&3, jj=(p>>6)&7, tt=(p>>9)&3;
        int k0 = 16*tt + 8*half + 2*qq;
        int n  = 8*jj + rr;
        split2(W1[k0*64+n], W1[(k0+1)*64+n], waHi[p], waLo[p]);
        split2(W2[k0*64+n], W2[(k0+1)*64+n], wbHi[p], wbLo[p]);
    }
    __syncthreads();

    // ---- RK4 (no CTA barriers: warps fully independent) ----
    const int nsteps = *nsp;
    const float dt  = 1.f / (float)nsteps;
    const float dt2 = 0.5f*dt, dt3 = dt/3.f, dt6 = dt/6.f;

    float wv[8][4], hacc[8][4];
#pragma unroll
    for (int j = 0; j < 8; ++j)
#pragma unroll
        for (int e = 0; e < 4; ++e) { wv[j][e] = h[j][e]; hacc[j][e] = 0.f; }

    const int nit = 4 * nsteps;
    for (int it = 0; it < nit; ++it) {
        int s = it & 3;
        gemm64(wv, waHi, waLo, c, q, r);            // U = A @ W1
#pragma unroll
        for (int j = 0; j < 8; ++j) {
            float2 bb = *reinterpret_cast<const float2*>(sm + PAR_B1 + 8*j + 2*q);
            wv[j][0] = tanhfast(c[j][0] + bb.x);
            wv[j][1] = tanhfast(c[j][1] + bb.y);
            wv[j][2] = tanhfast(c[j][2] + bb.x);
            wv[j][3] = tanhfast(c[j][3] + bb.y);
        }
        gemm64(wv, wbHi, wbLo, c, q, r);            // K = u @ W2
        float ca = (s==0 || s==3) ? dt6 : dt3;
        float cb = (s==2) ? dt : dt2;
#pragma unroll
        for (int j = 0; j < 8; ++j) {
            float2 bb = *reinterpret_cast<const float2*>(sm + PAR_B2 + 8*j + 2*q);
#pragma unroll
            for (int e = 0; e < 4; ++e) {
                float k  = c[j][e] + ((e&1) ? bb.y : bb.x);
                float hb = (s==0) ? h[j][e] : hacc[j][e];
                hb += ca * k;
                hacc[j][e] = hb;
                if (s == 3) { h[j][e] = hb; wv[j][e] = hb; }
                else        { wv[j][e] = h[j][e] + cb * k; }
            }
        }
    }

    // ---- GroupNorm2 ----
    float gn[8][4];
#pragma unroll
    for (int j = 0; j < 8; ++j) {
        float s1 = h[j][0] + h[j][1], s2 = h[j][0]*h[j][0] + h[j][1]*h[j][1];
        float t1 = h[j][2] + h[j][3], t2 = h[j][2]*h[j][2] + h[j][3]*h[j][3];
        s1 += __shfl_xor_sync(~0u, s1, 1); s1 += __shfl_xor_sync(~0u, s1, 2);
        s2 += __shfl_xor_sync(~0u, s2, 1); s2 += __shfl_xor_sync(~0u, s2, 2);
        t1 += __shfl_xor_sync(~0u, t1, 1); t1 += __shfl_xor_sync(~0u, t1, 2);
        t2 += __shfl_xor_sync(~0u, t2, 1); t2 += __shfl_xor_sync(~0u, t2, 2);
        float muA = s1*0.125f, vA = fmaxf(s2*0.125f - muA*muA, 0.f);
        float muB = t1*0.125f, vB = fmaxf(t2*0.125f - muB*muB, 0.f);
        float rsA = rsqrtf(vA + 1e-5f), rsB = rsqrtf(vB + 1e-5f);
        float2 gg = *reinterpret_cast<const float2*>(sm + PAR_G2  + 8*j + 2*q);
        float2 be = *reinterpret_cast<const float2*>(sm + PAR_BE2 + 8*j + 2*q);
        gn[j][0] = (h[j][0]-muA)*rsA*gg.x + be.x;
        gn[j][1] = (h[j][1]-muA)*rsA*gg.y + be.y;
        gn[j][2] = (h[j][2]-muB)*rsB*gg.x + be.x;
        gn[j][3] = (h[j][3]-muB)*rsB*gg.y + be.y;
    }

    // ---- logits = gn @ W_out (+ quad reduce), log_softmax, write ----
    float lgA[10], lgB[10];
#pragma unroll
    for (int m = 0; m < 10; ++m) { lgA[m]=0.f; lgB[m]=0.f; }
#pragma unroll
    for (int j = 0; j < 8; ++j) {
        const float* w0 = sm + PAR_WOUT + (8*j + 2*q) * 10;
        const float* w1 = w0 + 10;
#pragma unroll
        for (int m = 0; m < 10; ++m) {
            lgA[m] += gn[j][0]*w0[m] + gn[j][1]*w1[m];
            lgB[m] += gn[j][2]*w0[m] + gn[j][3]*w1[m];
        }
    }
#pragma unroll
    for (int m = 0; m < 10; ++m) {
        lgA[m] += __shfl_xor_sync(~0u, lgA[m], 1); lgA[m] += __shfl_xor_sync(~0u, lgA[m], 2);
        lgB[m] += __shfl_xor_sync(~0u, lgB[m], 1); lgB[m] += __shfl_xor_sync(~0u, lgB[m], 2);
        lgA[m] += sm[PAR_BOUT+m];
        lgB[m] += sm[PAR_BOUT+m];
    }
    if (q == 0) {
        float mxA = lgA[0], mxB = lgB[0];
#pragma unroll
        for (int m = 1; m < 10; ++m) { mxA = fmaxf(mxA, lgA[m]); mxB = fmaxf(mxB, lgB[m]); }
        float seA = 0.f, seB = 0.f;
#pragma unroll
        for (int m = 0; m < 10; ++m) { seA += expf(lgA[m]-mxA); seB += expf(lgB[m]-mxB); }
        float lseA = mxA + logf(seA), lseB = mxB + logf(seB);
        float* oa = out + (row0 + R0 + r) * 10;
        float* ob = out + (row0 + R0 + r + 8) * 10;
#pragma unroll
        for (int m = 0; m < 10; ++m) { oa[m] = lgA[m] - lseA; ob[m] = lgB[m] - lseB; }
    }
}

extern "C" void kernel_launch(void* const* d_in, const int* in_sizes, int n_in,
                              void* d_out, int out_size) {
    const float* x     = (const float*)d_in[0];
    const float* W_in  = (const float*)d_in[1];
    const float* b_in  = (const float*)d_in[2];
    const float* g1    = (const float*)d_in[3];
    const float* be1   = (const float*)d_in[4];
    const float* W1    = (const float*)d_in[5];
    const float* b1    = (const float*)d_in[6];
    const float* W2    = (const float*)d_in[7];
    const float* b2    = (const float*)d_in[8];
    const float* g2    = (const float*)d_in[9];
    const float* be2   = (const float*)d_in[10];
    const float* W_out = (const float*)d_in[11];
    const float* b_out = (const float*)d_in[12];
    const int*   nsp   = (const int*)d_in[13];
    float* out = (float*)d_out;

    const int B = in_sizes[0] / 784;
    const int nblk = B / ROWSB;
    const size_t smem = SMEM_FLOATS * sizeof(float);

    cudaFuncSetAttribute(node_mma_kernel,
                         cudaFuncAttributeMaxDynamicSharedMemorySize, (int)smem);
    node_mma_kernel<<<nblk, THREADS, smem>>>(
        x, W_in, b_in, g1, be1, W1, b1, W2, b2, g2, be2, W_out, b_out, nsp, out);
}